// round 2
// baseline (speedup 1.0000x reference)
#include <cuda_runtime.h>
#include <math.h>

// Problem constants (fixed-shape benchmark)
#define NN 50000
#define HH 16
#define RR 32
#define CC 8
#define EE 1600000

// Scratch (device globals; no allocation allowed)
__device__ float g_cnt[RR * NN];        // per-(rel,dst) edge counts, 6.4 MB
__device__ float g_x[NN * HH];          // layer-1 node features, 3.2 MB
__device__ float g_xw[RR * NN * CC];    // per-relation transformed feats, 51.2 MB

__device__ __forceinline__ void red_add_v4(float* addr, float4 v) {
    asm volatile("red.global.add.v4.f32 [%0], {%1,%2,%3,%4};"
                 :: "l"(addr), "f"(v.x), "f"(v.y), "f"(v.z), "f"(v.w)
                 : "memory");
}

// ---------------------------------------------------------------- init: zero cnt + x + out
__global__ void k_init(float* __restrict__ out) {
    int total = RR * NN + NN * HH + NN * CC;
    for (int i = blockIdx.x * blockDim.x + threadIdx.x; i < total;
         i += gridDim.x * blockDim.x) {
        if (i < RR * NN)                g_cnt[i] = 0.f;
        else if (i < RR * NN + NN * HH) g_x[i - RR * NN] = 0.f;
        else                            out[i - RR * NN - NN * HH] = 0.f;
    }
}

// ---------------------------------------------------------------- count edges per (rel,dst)
__global__ void k_count(const int* __restrict__ ei, const int* __restrict__ et) {
    int e = blockIdx.x * blockDim.x + threadIdx.x;
    if (e >= EE) return;
    int dst = ei[EE + e];
    int r   = et[e];
    atomicAdd(&g_cnt[r * NN + dst], 1.0f);
}

// ---------------------------------------------------------------- layer 1 scatter
// x[dst] += w1[rel, src] / cnt[rel, dst]
__global__ void __launch_bounds__(256)
k_layer1(const int* __restrict__ ei, const int* __restrict__ et,
         const float* __restrict__ w1) {
    int e = blockIdx.x * blockDim.x + threadIdx.x;
    if (e >= EE) return;
    int src = ei[e];
    int dst = ei[EE + e];
    int r   = et[e];
    float inv = __frcp_rn(fmaxf(g_cnt[r * NN + dst], 1.0f));
    const float4* w = (const float4*)(w1 + ((size_t)r * NN + (size_t)src) * HH);
    float* xp = g_x + dst * HH;
    #pragma unroll
    for (int i = 0; i < 4; i++) {
        float4 v = __ldg(&w[i]);
        v.x *= inv; v.y *= inv; v.z *= inv; v.w *= inv;
        red_add_v4(xp + i * 4, v);
    }
}

// ---------------------------------------------------------------- activation (float4): x = relu(x + root1 + b1)
__global__ void k_act(const float* __restrict__ root1, const float* __restrict__ b1) {
    int i = blockIdx.x * blockDim.x + threadIdx.x;   // over NN*4 float4s
    if (i >= NN * 4) return;
    float4 xv = ((float4*)g_x)[i];
    float4 rv = __ldg(((const float4*)root1) + i);
    float4 bv = __ldg(((const float4*)b1) + (i & 3));
    xv.x = fmaxf(xv.x + rv.x + bv.x, 0.f);
    xv.y = fmaxf(xv.y + rv.y + bv.y, 0.f);
    xv.z = fmaxf(xv.z + rv.z + bv.z, 0.f);
    xv.w = fmaxf(xv.w + rv.w + bv.w, 0.f);
    ((float4*)g_x)[i] = xv;
}

// ---------------------------------------------------------------- xw materialization
// xw[r, n, :] = x[n, :] @ w2[r]   (thread per (r,n), n-major -> coalesced)
__global__ void __launch_bounds__(256)
k_xw(const float* __restrict__ w2) {
    __shared__ float sw[2 * HH * CC];   // at most 2 relations per 256-thread block
    int idx0 = blockIdx.x * 256;
    int r0 = idx0 / NN;
    int r1 = (idx0 + 255) / NN;         // inclusive; r1 - r0 <= 1
    int nrel = r1 - r0 + 1;
    for (int i = threadIdx.x; i < nrel * HH * CC; i += 256)
        sw[i] = w2[r0 * HH * CC + i];
    __syncthreads();

    int idx = idx0 + threadIdx.x;       // over RR*NN
    if (idx >= RR * NN) return;
    int r = idx / NN;
    int n = idx - r * NN;
    const float4* xp = (const float4*)(g_x + n * HH);
    const float* w = sw + (r - r0) * HH * CC;

    float acc[CC];
    #pragma unroll
    for (int c = 0; c < CC; c++) acc[c] = 0.f;

    #pragma unroll
    for (int i4 = 0; i4 < 4; i4++) {
        float4 xv = xp[i4];
        float xs[4] = {xv.x, xv.y, xv.z, xv.w};
        #pragma unroll
        for (int j = 0; j < 4; j++) {
            int h = i4 * 4 + j;
            #pragma unroll
            for (int c = 0; c < CC; c++)
                acc[c] += xs[j] * w[h * CC + c];   // warp-uniform -> broadcast LDS
        }
    }
    float4* op = (float4*)(g_xw + (size_t)idx * CC);
    op[0] = make_float4(acc[0], acc[1], acc[2], acc[3]);
    op[1] = make_float4(acc[4], acc[5], acc[6], acc[7]);
}

// ---------------------------------------------------------------- layer 2 scatter
// out[dst] += xw[rel, src] / cnt[rel, dst]   (32B aligned L2-resident gather)
__global__ void __launch_bounds__(256)
k_layer2(const int* __restrict__ ei, const int* __restrict__ et,
         float* __restrict__ out) {
    int e = blockIdx.x * blockDim.x + threadIdx.x;
    if (e >= EE) return;
    int src = ei[e];
    int dst = ei[EE + e];
    int r   = et[e];
    float inv = __frcp_rn(fmaxf(g_cnt[r * NN + dst], 1.0f));
    const float4* xwp = (const float4*)(g_xw + ((size_t)r * NN + (size_t)src) * CC);
    float4 v0 = __ldg(&xwp[0]);
    float4 v1 = __ldg(&xwp[1]);
    v0.x *= inv; v0.y *= inv; v0.z *= inv; v0.w *= inv;
    v1.x *= inv; v1.y *= inv; v1.z *= inv; v1.w *= inv;
    red_add_v4(out + dst * CC, v0);
    red_add_v4(out + dst * CC + 4, v1);
}

// ---------------------------------------------------------------- finalize: + x@root2 + b2, log_softmax
__global__ void k_final(const float* __restrict__ root2, const float* __restrict__ b2,
                        float* __restrict__ out) {
    int n = blockIdx.x * blockDim.x + threadIdx.x;
    if (n >= NN) return;
    const float4* xp = (const float4*)(g_x + n * HH);
    float o[CC];
    #pragma unroll
    for (int c = 0; c < CC; c++) o[c] = out[n * CC + c] + __ldg(&b2[c]);

    #pragma unroll
    for (int i4 = 0; i4 < 4; i4++) {
        float4 xv = xp[i4];
        float xs[4] = {xv.x, xv.y, xv.z, xv.w};
        #pragma unroll
        for (int j = 0; j < 4; j++) {
            int h = i4 * 4 + j;
            #pragma unroll
            for (int c = 0; c < CC; c++)
                o[c] += xs[j] * __ldg(&root2[h * CC + c]);
        }
    }
    float m = o[0];
    #pragma unroll
    for (int c = 1; c < CC; c++) m = fmaxf(m, o[c]);
    float s = 0.0f;
    #pragma unroll
    for (int c = 0; c < CC; c++) s += expf(o[c] - m);
    float l = logf(s) + m;
    #pragma unroll
    for (int c = 0; c < CC; c++) out[n * CC + c] = o[c] - l;
}

// ---------------------------------------------------------------- launch
extern "C" void kernel_launch(void* const* d_in, const int* in_sizes, int n_in,
                              void* d_out, int out_size) {
    const int*   ei    = (const int*)  d_in[0];  // [2, E]
    const int*   et    = (const int*)  d_in[1];  // [E]
    const float* w1    = (const float*)d_in[2];  // [R, N, H]
    const float* root1 = (const float*)d_in[3];  // [N, H]
    const float* b1    = (const float*)d_in[4];  // [H]
    const float* w2    = (const float*)d_in[5];  // [R, H, C]
    const float* root2 = (const float*)d_in[6];  // [H, C]
    const float* b2    = (const float*)d_in[7];  // [C]
    float* out = (float*)d_out;                  // [N, C]

    k_init  <<<512, 256>>>(out);
    k_count <<<(EE + 255) / 256, 256>>>(ei, et);
    k_layer1<<<(EE + 255) / 256, 256>>>(ei, et, w1);
    k_act   <<<(NN * 4 + 255) / 256, 256>>>(root1, b1);
    k_xw    <<<(RR * NN + 255) / 256, 256>>>(w2);
    k_layer2<<<(EE + 255) / 256, 256>>>(ei, et, out);
    k_final <<<(NN + 255) / 256, 256>>>(root2, b2, out);
}

// round 5
// speedup vs baseline: 1.0091x; 1.0091x over previous
#include <cuda_runtime.h>
#include <math.h>

// Problem constants (fixed-shape benchmark)
#define NN 50000
#define HH 16
#define RR 32
#define CC 8
#define EE 1600000

// Scratch (device globals; no allocation allowed)
__device__ float g_cnt[RR * NN];   // per-(rel,dst) edge counts, 6.4 MB
__device__ float g_x[NN * HH];     // layer-1 node features, 3.2 MB

__device__ __forceinline__ void red_add_v4(float* addr, float4 v) {
    asm volatile("red.global.add.v4.f32 [%0], {%1,%2,%3,%4};"
                 :: "l"(addr), "f"(v.x), "f"(v.y), "f"(v.z), "f"(v.w)
                 : "memory");
}

// ---------------------------------------------------------------- (0) zero cnt
__global__ void k_zero_cnt() {
    int i = blockIdx.x * blockDim.x + threadIdx.x;
    if (i < RR * NN / 4) ((float4*)g_cnt)[i] = make_float4(0.f, 0.f, 0.f, 0.f);
}

// ---------------------------------------------------------------- (1) count edges per (rel,dst)
__global__ void k_count(const int* __restrict__ ei, const int* __restrict__ et) {
    int e = blockIdx.x * blockDim.x + threadIdx.x;
    if (e >= EE) return;
    int dst = ei[EE + e];
    int r   = et[e];
    atomicAdd(&g_cnt[r * NN + dst], 1.0f);
}

// ---------------------------------------------------------------- (2) zero x + out
__global__ void k_zero_x_out(float* __restrict__ out) {
    int i = blockIdx.x * blockDim.x + threadIdx.x;
    int nx = NN * HH / 4;
    int no = NN * CC / 4;
    if (i < nx)            ((float4*)g_x)[i] = make_float4(0.f, 0.f, 0.f, 0.f);
    else if (i < nx + no)  ((float4*)out)[i - nx] = make_float4(0.f, 0.f, 0.f, 0.f);
}

// ---------------------------------------------------------------- (3) layer 1 scatter, 2 edges/thread
// x[dst] += w1[rel, src] / cnt[rel, dst]
__global__ void __launch_bounds__(256)
k_layer1(const int* __restrict__ ei, const int* __restrict__ et,
         const float* __restrict__ w1) {
    int t = blockIdx.x * blockDim.x + threadIdx.x;   // over EE/2
    if (t >= EE / 2) return;
    int2 s  = __ldg(((const int2*)ei) + t);
    int2 d  = __ldg(((const int2*)(ei + EE)) + t);
    int2 rt = __ldg(((const int2*)et) + t);

    float inv0 = __frcp_rn(fmaxf(g_cnt[rt.x * NN + d.x], 1.0f));
    float inv1 = __frcp_rn(fmaxf(g_cnt[rt.y * NN + d.y], 1.0f));

    const float4* wa = (const float4*)(w1 + ((size_t)rt.x * NN + (size_t)s.x) * HH);
    const float4* wb = (const float4*)(w1 + ((size_t)rt.y * NN + (size_t)s.y) * HH);

    float4 a0 = __ldg(&wa[0]), a1 = __ldg(&wa[1]), a2 = __ldg(&wa[2]), a3 = __ldg(&wa[3]);
    float4 b0 = __ldg(&wb[0]), b1 = __ldg(&wb[1]), b2 = __ldg(&wb[2]), b3 = __ldg(&wb[3]);

    float* xa = g_x + d.x * HH;
    float* xb = g_x + d.y * HH;
    a0.x*=inv0;a0.y*=inv0;a0.z*=inv0;a0.w*=inv0; red_add_v4(xa+ 0, a0);
    a1.x*=inv0;a1.y*=inv0;a1.z*=inv0;a1.w*=inv0; red_add_v4(xa+ 4, a1);
    a2.x*=inv0;a2.y*=inv0;a2.z*=inv0;a2.w*=inv0; red_add_v4(xa+ 8, a2);
    a3.x*=inv0;a3.y*=inv0;a3.z*=inv0;a3.w*=inv0; red_add_v4(xa+12, a3);
    b0.x*=inv1;b0.y*=inv1;b0.z*=inv1;b0.w*=inv1; red_add_v4(xb+ 0, b0);
    b1.x*=inv1;b1.y*=inv1;b1.z*=inv1;b1.w*=inv1; red_add_v4(xb+ 4, b1);
    b2.x*=inv1;b2.y*=inv1;b2.z*=inv1;b2.w*=inv1; red_add_v4(xb+ 8, b2);
    b3.x*=inv1;b3.y*=inv1;b3.z*=inv1;b3.w*=inv1; red_add_v4(xb+12, b3);
}

// ---------------------------------------------------------------- (4) activation (float4)
__global__ void k_act(const float* __restrict__ root1, const float* __restrict__ b1) {
    int i = blockIdx.x * blockDim.x + threadIdx.x;   // over NN*4 float4s
    if (i >= NN * 4) return;
    float4 xv = ((float4*)g_x)[i];
    float4 rv = __ldg(((const float4*)root1) + i);
    float4 bv = __ldg(((const float4*)b1) + (i & 3));
    xv.x = fmaxf(xv.x + rv.x + bv.x, 0.f);
    xv.y = fmaxf(xv.y + rv.y + bv.y, 0.f);
    xv.z = fmaxf(xv.z + rv.z + bv.z, 0.f);
    xv.w = fmaxf(xv.w + rv.w + bv.w, 0.f);
    ((float4*)g_x)[i] = xv;
}

// ---------------------------------------------------------------- (5) layer 2 scatter
// out[dst] += (x[src] @ w2[rel]) / cnt[rel, dst]
// w2 in smem as [hc][rel] stride 33 -> random-rel lanes hit distinct banks.
__global__ void __launch_bounds__(256)
k_layer2(const int* __restrict__ ei, const int* __restrict__ et,
         const float* __restrict__ w2, float* __restrict__ out) {
    __shared__ float sw[HH * CC * 33];  // 16.9 KB
    for (int i = threadIdx.x; i < RR * HH * CC; i += blockDim.x) {
        int rel = i >> 7;
        int hc  = i & 127;
        sw[hc * 33 + rel] = w2[i];
    }
    __syncthreads();

    for (int e = blockIdx.x * blockDim.x + threadIdx.x; e < EE;
         e += gridDim.x * blockDim.x) {
        int src = __ldg(ei + e);
        int dst = __ldg(ei + EE + e);
        int r   = __ldg(et + e);
        float inv = __frcp_rn(fmaxf(g_cnt[r * NN + dst], 1.0f));

        const float4* xp = (const float4*)(g_x + src * HH);
        float acc[CC];
        #pragma unroll
        for (int c = 0; c < CC; c++) acc[c] = 0.0f;

        #pragma unroll
        for (int i4 = 0; i4 < 4; i4++) {
            float4 xv = __ldg(&xp[i4]);
            float xs[4] = {xv.x, xv.y, xv.z, xv.w};
            #pragma unroll
            for (int j = 0; j < 4; j++) {
                int h = i4 * 4 + j;
                #pragma unroll
                for (int c = 0; c < CC; c++)
                    acc[c] += xs[j] * sw[(h * CC + c) * 33 + r];
            }
        }
        float4 v0 = make_float4(acc[0]*inv, acc[1]*inv, acc[2]*inv, acc[3]*inv);
        float4 v1 = make_float4(acc[4]*inv, acc[5]*inv, acc[6]*inv, acc[7]*inv);
        red_add_v4(out + dst * CC, v0);
        red_add_v4(out + dst * CC + 4, v1);
    }
}

// ---------------------------------------------------------------- (6) finalize
__global__ void k_final(const float* __restrict__ root2, const float* __restrict__ b2,
                        float* __restrict__ out) {
    int n = blockIdx.x * blockDim.x + threadIdx.x;
    if (n >= NN) return;
    const float4* xp = (const float4*)(g_x + n * HH);
    float o[CC];
    #pragma unroll
    for (int c = 0; c < CC; c++) o[c] = out[n * CC + c] + __ldg(&b2[c]);

    #pragma unroll
    for (int i4 = 0; i4 < 4; i4++) {
        float4 xv = xp[i4];
        float xs[4] = {xv.x, xv.y, xv.z, xv.w};
        #pragma unroll
        for (int j = 0; j < 4; j++) {
            int h = i4 * 4 + j;
            #pragma unroll
            for (int c = 0; c < CC; c++)
                o[c] += xs[j] * __ldg(&root2[h * CC + c]);
        }
    }
    float m = o[0];
    #pragma unroll
    for (int c = 1; c < CC; c++) m = fmaxf(m, o[c]);
    float s = 0.0f;
    #pragma unroll
    for (int c = 0; c < CC; c++) s += expf(o[c] - m);
    float l = logf(s) + m;
    #pragma unroll
    for (int c = 0; c < CC; c++) out[n * CC + c] = o[c] - l;
}

// ---------------------------------------------------------------- launch
extern "C" void kernel_launch(void* const* d_in, const int* in_sizes, int n_in,
                              void* d_out, int out_size) {
    const int*   ei    = (const int*)  d_in[0];  // [2, E]
    const int*   et    = (const int*)  d_in[1];  // [E]
    const float* w1    = (const float*)d_in[2];  // [R, N, H]
    const float* root1 = (const float*)d_in[3];  // [N, H]
    const float* b1    = (const float*)d_in[4];  // [H]
    const float* w2    = (const float*)d_in[5];  // [R, H, C]
    const float* root2 = (const float*)d_in[6];  // [H, C]
    const float* b2    = (const float*)d_in[7];  // [C]
    float* out = (float*)d_out;                  // [N, C]

    k_zero_cnt  <<<(RR * NN / 4 + 255) / 256, 256>>>();
    k_count     <<<(EE + 255) / 256, 256>>>(ei, et);
    k_zero_x_out<<<((NN * HH + NN * CC) / 4 + 255) / 256, 256>>>(out);
    k_layer1    <<<(EE / 2 + 255) / 256, 256>>>(ei, et, w1);   // launch idx 3 -> profiled
    k_act       <<<(NN * 4 + 255) / 256, 256>>>(root1, b1);
    k_layer2    <<<2048, 256>>>(ei, et, w2, out);
    k_final     <<<(NN + 255) / 256, 256>>>(root2, b2, out);
}